// round 16
// baseline (speedup 1.0000x reference)
#include <cuda_runtime.h>
#include <cuda_fp16.h>
#include <cstdint>

// SigmaModel via tensor cores: mma.sync.m16n8k16 fp16 (single-term H, fp16 W2).
// R16: double-buffered tri chunks + warp-specialized P1 overlapped with epilogue.
// h = relu([s,a] @ W1^T + b1); tri = h @ W2^T + b2;
// out[b,i,j] = tri[t(min,max)], diag -> exp.
// 152 persistent CTAs, 1024 threads.

#define BATCH   131072
#define SDIM    32
#define ADIM    8
#define INDIM   40
#define HID     64
#define TRI     528
#define ROWS    64                // rows per tile
#define NT      1024
#define GRID    152
#define NTILES  (BATCH / ROWS)    // 2048
#define NCOLS   576               // padded tri cols (8 warps x 72)
#define WS32    36                // u32 words per W2/H row (rows +4 banks)
#define TPAD    584               // tri chunk stride
#define XPAD    44                // X/W1 row stride (44 mod 32 = 12 -> banked)
#define TRIBUF  9344              // floats per tri chunk buffer (16*TPAD)

// ---- smem byte offsets ----
#define OFF_W2H  0                // fp16 [576][72] = 82944
#define OFF_HH   82944            // fp16 [64][72] = 9216
#define OFF_TRI  92160            // f32 2 x [16][TPAD] = 74752 (A, B=+37376)
#define OFF_X    166912           // f32 [64][44] = 11264
#define OFF_W1   178176           // f32 [64][44] = 11264 (W1 native k-major)
#define OFF_B1   189440           // f32 [64] (pad 256)
#define OFF_B2   189696           // f32 [576] = 2304
#define OFF_TBL  192000           // int [1024] = 4096
#define SMEM_BYTES 196096

typedef unsigned long long u64;

__device__ __forceinline__ void unpack2(u64 v, float& lo, float& hi) {
    asm("mov.b64 {%0, %1}, %2;" : "=f"(lo), "=f"(hi) : "l"(v));
}
__device__ __forceinline__ u64 pack2(float lo, float hi) {
    u64 r; asm("mov.b64 %0, {%1, %2};" : "=l"(r) : "f"(lo), "f"(hi)); return r;
}
__device__ __forceinline__ void fma2(u64& d, u64 a, u64 b) {
    asm("fma.rn.f32x2 %0, %1, %2, %0;" : "+l"(d) : "l"(a), "l"(b));
}
__device__ __forceinline__ uint32_t smem_u32p(const void* p) {
    uint32_t r;
    asm("{ .reg .u64 t; cvta.to.shared.u64 t, %1; cvt.u32.u64 %0, t; }" : "=r"(r) : "l"(p));
    return r;
}
__device__ __forceinline__ void cp16(uint32_t dst, const void* src) {
    asm volatile("cp.async.ca.shared.global [%0], [%1], 16;" :: "r"(dst), "l"(src));
}
__device__ __forceinline__ void cp_commit() {
    asm volatile("cp.async.commit_group;" ::: "memory");
}
__device__ __forceinline__ void cp_wait0() {
    asm volatile("cp.async.wait_group 0;" ::: "memory");
}
__device__ __forceinline__ void ldsm4(uint32_t* r, uint32_t a) {
    asm volatile("ldmatrix.sync.aligned.m8n8.x4.shared.b16 {%0,%1,%2,%3}, [%4];"
                 : "=r"(r[0]), "=r"(r[1]), "=r"(r[2]), "=r"(r[3]) : "r"(a));
}
__device__ __forceinline__ void ldsm2(uint32_t* r, uint32_t a) {
    asm volatile("ldmatrix.sync.aligned.m8n8.x2.shared.b16 {%0,%1}, [%2];"
                 : "=r"(r[0]), "=r"(r[1]) : "r"(a));
}
__device__ __forceinline__ void mma_f16(float* c, const uint32_t* a,
                                        uint32_t b0, uint32_t b1) {
    asm("mma.sync.aligned.m16n8k16.row.col.f32.f16.f16.f32 "
        "{%0,%1,%2,%3},{%4,%5,%6,%7},{%8,%9},{%0,%1,%2,%3};"
        : "+f"(c[0]), "+f"(c[1]), "+f"(c[2]), "+f"(c[3])
        : "r"(a[0]), "r"(a[1]), "r"(a[2]), "r"(a[3]), "r"(b0), "r"(b1));
}
__device__ __forceinline__ uint32_t hfpack(float x, float y) {
    __half2 h = __floats2half2_rn(x, y);
    return *reinterpret_cast<uint32_t*>(&h);
}

// P1 for 256 threads (warps 0-7): H = relu(X @ W1^T + b1) -> fp16.
// Thread: rows r0,r0+1 x cols c0..c0+7. Accs hold (even-k, odd-k) partials.
__device__ __forceinline__ void p1_compute(const float* sX, const float* sW1,
                                           const float* sB1, uint32_t* HH32,
                                           int tid) {
    const int pw = tid >> 5, pl = tid & 31;
    const int rp = pl >> 3, cg = pl & 7;
    const int r0 = pw * 8 + rp * 2;
    const int c0 = cg * 8;
    u64 accA[8], accB[8];
#pragma unroll
    for (int c8 = 0; c8 < 8; ++c8) {
        accA[c8] = pack2(sB1[c0 + c8], 0.f);
        accB[c8] = accA[c8];
    }
    const ulonglong2* xr0 = reinterpret_cast<const ulonglong2*>(&sX[r0 * XPAD]);
    const ulonglong2* xr1 = reinterpret_cast<const ulonglong2*>(&sX[(r0 + 1) * XPAD]);
#pragma unroll
    for (int k4 = 0; k4 < 10; ++k4) {
        const ulonglong2 xa = xr0[k4];
        const ulonglong2 xb = xr1[k4];
#pragma unroll
        for (int c8 = 0; c8 < 8; ++c8) {
            const ulonglong2 w =
                *reinterpret_cast<const ulonglong2*>(&sW1[(c0 + c8) * XPAD + k4 * 4]);
            fma2(accA[c8], xa.x, w.x); fma2(accA[c8], xa.y, w.y);
            fma2(accB[c8], xb.x, w.x); fma2(accB[c8], xb.y, w.y);
        }
    }
    float hA[8], hB[8];
#pragma unroll
    for (int c8 = 0; c8 < 8; ++c8) {
        float e, o;
        unpack2(accA[c8], e, o); hA[c8] = fmaxf(e + o, 0.f);
        unpack2(accB[c8], e, o); hB[c8] = fmaxf(e + o, 0.f);
    }
    const int wbase = (c0 >> 1);
#pragma unroll
    for (int q = 0; q < 4; ++q) {
        HH32[r0 * WS32 + wbase + q]       = hfpack(hA[2 * q], hA[2 * q + 1]);
        HH32[(r0 + 1) * WS32 + wbase + q] = hfpack(hB[2 * q], hB[2 * q + 1]);
    }
}

__global__ void __launch_bounds__(NT, 1)
sigma_mma_kernel(const float* __restrict__ s,
                 const float* __restrict__ a,
                 const float* __restrict__ W1,
                 const float* __restrict__ b1,
                 const float* __restrict__ W2,
                 const float* __restrict__ b2,
                 float* __restrict__ out) {
    extern __shared__ char smem[];
    uint32_t* W2H32 = (uint32_t*)(smem + OFF_W2H);
    uint32_t* HH32  = (uint32_t*)(smem + OFF_HH);
    float*    sTri  = (float*)(smem + OFF_TRI);
    float*    sX    = (float*)(smem + OFF_X);
    float*    sW1   = (float*)(smem + OFF_W1);
    float*    sB1   = (float*)(smem + OFF_B1);
    float*    sB2   = (float*)(smem + OFF_B2);
    int*      sTbl  = (int*)(smem + OFF_TBL);

    const int tid = threadIdx.x;
    const uint32_t sXaddr = smem_u32p(sX);

    // ================= one-time staging =================
    for (int idx = tid; idx < TRI * 32; idx += NT) {
        int t = idx >> 5, kw = idx & 31;
        float2 w = *reinterpret_cast<const float2*>(&W2[t * HID + kw * 2]);
        W2H32[t * WS32 + kw] = hfpack(w.x, w.y);
    }
    for (int idx = tid; idx < (NCOLS - TRI) * WS32; idx += NT) {
        int t = TRI + idx / WS32, kw = idx % WS32;
        W2H32[t * WS32 + kw] = 0u;
    }
    for (int idx = tid; idx < HID * 10; idx += NT) {
        int hh = idx / 10, k4 = idx - hh * 10;
        float4 w = *reinterpret_cast<const float4*>(&W1[hh * INDIM + k4 * 4]);
        *reinterpret_cast<float4*>(&sW1[hh * XPAD + k4 * 4]) = w;
    }
    if (tid < HID) sB1[tid] = b1[tid];
    for (int idx = tid; idx < NCOLS; idx += NT)
        sB2[idx] = (idx < TRI) ? b2[idx] : 0.0f;
    for (int o = tid; o < 1024; o += NT) {
        int i = o >> 5, j = o & 31;
        int ii = (i < j) ? i : j;
        int jj = (i < j) ? j : i;
        int t = ii * 32 - ((ii * (ii + 1)) >> 1) + jj;
        sTbl[o] = t | ((i == j) ? (1 << 16) : 0);
    }

    // prefetch X for first tile
    const int tile0 = blockIdx.x;
    {
        int row0 = tile0 * ROWS;
        if (tid < 512) {
            int r = tid >> 3, c4 = tid & 7;
            cp16(sXaddr + (r * XPAD + c4 * 4) * 4, &s[(size_t)(row0 + r) * SDIM + c4 * 4]);
        } else if (tid < 640) {
            int t2 = tid - 512, r2 = t2 >> 1, d4 = t2 & 1;
            cp16(sXaddr + (r2 * XPAD + SDIM + d4 * 4) * 4,
                 &a[(size_t)(row0 + r2) * ADIM + d4 * 4]);
        }
        cp_commit();
    }
    cp_wait0();
    __syncthreads();

    // MMA mapping: 32 warps = 4 M-blocks(16r) x 8 N-blocks(72c = 9 n8-tiles).
    const int wi   = tid >> 5, lane = tid & 31;
    const int rb   = wi >> 3,  cb   = wi & 7;
    const int l4   = lane >> 2, lm  = lane & 3;
    const int wcol = cb * 72;

    const uint32_t hhBase = smem_u32p(HH32);
    const uint32_t w2Base = smem_u32p(W2H32);
    const uint32_t aAddr = hhBase +
        (((rb * 16 + (lane & 15)) * WS32 + ((lane >> 4) << 2)) << 2);
    const uint32_t bAddr = w2Base +
        (((wcol + (lane & 7) + ((lane & 16) >> 1)) * WS32 + (((lane >> 3) & 1) << 2)) << 2);
    const uint32_t b8Addr = w2Base +
        (((wcol + 64 + (lane & 7)) * WS32 + (((lane >> 3) & 1) << 2)) << 2);

    // hoisted scatter constants (tile-invariant)
    const int4 tt = ((const int4*)sTbl)[tid & 255];
    const int to0 = tt.x & 0xffff, to1 = tt.y & 0xffff;
    const int to2 = tt.z & 0xffff, to3 = tt.w & 0xffff;
    const int fl0 = tt.x >> 16, fl1 = tt.y >> 16, fl2 = tt.z >> 16, fl3 = tt.w >> 16;
    const float* const trA = &sTri[(tid >> 8) * TPAD];       // buffer A
    const float* const trB = trA + TRIBUF;                   // buffer B
    // writer pointers: stage rb writes buffer (rb & 1)
    float* const trW0 = &sTri[(rb & 1) * TRIBUF + l4 * TPAD + wcol + 2 * lm];
    float* const trW1 = trW0 + 8 * TPAD;

    // prologue: P1(tile0)
    if (tid < 256) p1_compute(sX, sW1, sB1, HH32, tid);
    __syncthreads();

    // ================= persistent tile loop =================
#pragma unroll 1
    for (int tile = tile0; tile < NTILES; tile += GRID) {
        const int row0 = tile * ROWS;
        const bool hasNext = (tile + GRID < NTILES);

        // ---- issue prefetch of X(t+1) (lands during GEMM) ----
        if (hasNext) {
            int nrow0 = (tile + GRID) * ROWS;
            if (tid < 512) {
                int r = tid >> 3, c4 = tid & 7;
                cp16(sXaddr + (r * XPAD + c4 * 4) * 4,
                     &s[(size_t)(nrow0 + r) * SDIM + c4 * 4]);
            } else if (tid < 640) {
                int t2 = tid - 512, r2 = t2 >> 1, d4 = t2 & 1;
                cp16(sXaddr + (r2 * XPAD + SDIM + d4 * 4) * 4,
                     &a[(size_t)(nrow0 + r2) * ADIM + d4 * 4]);
            }
            cp_commit();
        }

        // ---- GEMM: tri = H @ W2^T + b2 (HMMA fp16) ----
        float c[9][4];
#pragma unroll
        for (int j = 0; j < 9; ++j) {
            float2 bb = *reinterpret_cast<const float2*>(&sB2[wcol + j * 8 + 2 * lm]);
            c[j][0] = bb.x; c[j][1] = bb.y;
            c[j][2] = bb.x; c[j][3] = bb.y;
        }
#pragma unroll
        for (int kk = 0; kk < 4; ++kk) {
            const uint32_t kb = kk * 32;
            uint32_t ah[4];
            ldsm4(ah, aAddr + kb);
#pragma unroll
            for (int p = 0; p < 4; ++p) {
                uint32_t bh[4];
                ldsm4(bh, bAddr + p * 2304 + kb);
                mma_f16(c[2 * p],     ah, bh[0], bh[1]);
                mma_f16(c[2 * p + 1], ah, bh[2], bh[3]);
            }
            {
                uint32_t bh[2];
                ldsm2(bh, b8Addr + kb);
                mma_f16(c[8], ah, bh[0], bh[1]);
            }
        }

        // ---- writer stage 0 -> buffer A (rb==0; its c dies here) ----
        if (rb == 0) {
#pragma unroll
            for (int j = 0; j < 9; ++j) {
                *reinterpret_cast<float2*>(trW0 + j * 8) = make_float2(c[j][0], c[j][1]);
                *reinterpret_cast<float2*>(trW1 + j * 8) = make_float2(c[j][2], c[j][3]);
            }
        }
        cp_wait0();
        __syncthreads();   // X(t+1) visible; chunk A ready; HH free

        // ---- region 0: P1(t+1) on warps 0-7  ||  scatter st0 + writer st1 ----
        if (tid < 256) {
            if (hasNext) p1_compute(sX, sW1, sB1, HH32, tid);
        } else {
            if (rb == 1) {
#pragma unroll
                for (int j = 0; j < 9; ++j) {
                    *reinterpret_cast<float2*>(trW0 + j * 8) = make_float2(c[j][0], c[j][1]);
                    *reinterpret_cast<float2*>(trW1 + j * 8) = make_float2(c[j][2], c[j][3]);
                }
            }
            // scatter stage 0 from buffer A: 768 threads, rows strided by 3
            float4* out4 = reinterpret_cast<float4*>(out + (size_t)row0 * 1024);
            const int rstart = (tid >> 8) - 1;   // 0..2
            const int o4 = tid & 255;
#pragma unroll
            for (int it = 0; it < 6; ++it) {
                const int r = rstart + 3 * it;
                if (r < 16) {
                    const float* tr = &sTri[r * TPAD];
                    float v0 = tr[to0], v1 = tr[to1], v2 = tr[to2], v3 = tr[to3];
                    if (fl0) v0 = __expf(v0);
                    if (fl1) v1 = __expf(v1);
                    if (fl2) v2 = __expf(v2);
                    if (fl3) v3 = __expf(v3);
                    out4[r * 256 + o4] = make_float4(v0, v1, v2, v3);
                }
            }
        }
        __syncthreads();

        // ---- regions 1-3: scatter st from buf(st&1), writer st+1 overlapped ----
#pragma unroll
        for (int st = 1; st < 4; ++st) {
            if (st < 3 && rb == st + 1) {
#pragma unroll
                for (int j = 0; j < 9; ++j) {
                    *reinterpret_cast<float2*>(trW0 + j * 8) = make_float2(c[j][0], c[j][1]);
                    *reinterpret_cast<float2*>(trW1 + j * 8) = make_float2(c[j][2], c[j][3]);
                }
            }
            const float* trS = (st & 1) ? trB : trA;
            float4* out4 = reinterpret_cast<float4*>(out + (size_t)(row0 + st * 16) * 1024);
#pragma unroll
            for (int it = 0; it < 4; ++it) {
                const float* tr = trS + it * 4 * TPAD;
                float v0 = tr[to0], v1 = tr[to1], v2 = tr[to2], v3 = tr[to3];
                if (fl0) v0 = __expf(v0);
                if (fl1) v1 = __expf(v1);
                if (fl2) v2 = __expf(v2);
                if (fl3) v3 = __expf(v3);
                out4[tid + it * NT] = make_float4(v0, v1, v2, v3);
            }
            __syncthreads();
        }
    }
}

extern "C" void kernel_launch(void* const* d_in, const int* in_sizes, int n_in,
                              void* d_out, int out_size) {
    (void)in_sizes; (void)n_in; (void)out_size;
    const float* s  = (const float*)d_in[0];
    const float* a  = (const float*)d_in[1];
    const float* W1 = (const float*)d_in[2];
    const float* b1 = (const float*)d_in[3];
    const float* W2 = (const float*)d_in[4];
    const float* b2 = (const float*)d_in[5];
    float* out = (float*)d_out;

    cudaFuncSetAttribute(sigma_mma_kernel,
                         cudaFuncAttributeMaxDynamicSharedMemorySize, SMEM_BYTES);
    sigma_mma_kernel<<<GRID, NT, SMEM_BYTES>>>(s, a, W1, b1, W2, b2, out);
}

// round 17
// speedup vs baseline: 1.7682x; 1.7682x over previous
#include <cuda_runtime.h>
#include <cuda_fp16.h>
#include <cstdint>

// SigmaModel via tensor cores: mma.sync.m16n8k16 fp16 (single-term H, fp16 W2).
// R17 = R15 + 32-row tri chunks (2 epilogue stages, 5 barriers/tile).
// h = relu([s,a] @ W1^T + b1); tri = h @ W2^T + b2;
// out[b,i,j] = tri[t(min,max)], diag -> exp.
// 152 persistent CTAs, 1024 threads.

#define BATCH   131072
#define SDIM    32
#define ADIM    8
#define INDIM   40
#define HID     64
#define TRI     528
#define ROWS    64                // rows per tile
#define NT      1024
#define GRID    152
#define NTILES  (BATCH / ROWS)    // 2048
#define NCOLS   576               // padded tri cols (8 warps x 72)
#define WS32    36                // u32 words per W2/H row (rows +4 banks)
#define TPAD    584               // tri chunk stride
#define XPAD    44                // X/W1 row stride (44 mod 32 = 12 -> banked)

// ---- smem byte offsets ----
#define OFF_W2H  0                // fp16 [576][72] = 82944
#define OFF_HH   82944            // fp16 [64][72] = 9216
#define OFF_TRI  92160            // f32 [32][TPAD] = 74752
#define OFF_X    166912           // f32 [64][44] = 11264
#define OFF_W1   178176           // f32 [64][44] = 11264 (W1 native k-major)
#define OFF_B1   189440           // f32 [64] (pad 256)
#define OFF_B2   189696           // f32 [576] = 2304
#define OFF_TBL  192000           // int [1024] = 4096
#define SMEM_BYTES 196096

typedef unsigned long long u64;

__device__ __forceinline__ void unpack2(u64 v, float& lo, float& hi) {
    asm("mov.b64 {%0, %1}, %2;" : "=f"(lo), "=f"(hi) : "l"(v));
}
__device__ __forceinline__ u64 pack2(float lo, float hi) {
    u64 r; asm("mov.b64 %0, {%1, %2};" : "=l"(r) : "f"(lo), "f"(hi)); return r;
}
__device__ __forceinline__ void fma2(u64& d, u64 a, u64 b) {
    asm("fma.rn.f32x2 %0, %1, %2, %0;" : "+l"(d) : "l"(a), "l"(b));
}
__device__ __forceinline__ uint32_t smem_u32p(const void* p) {
    uint32_t r;
    asm("{ .reg .u64 t; cvta.to.shared.u64 t, %1; cvt.u32.u64 %0, t; }" : "=r"(r) : "l"(p));
    return r;
}
__device__ __forceinline__ void cp16(uint32_t dst, const void* src) {
    asm volatile("cp.async.ca.shared.global [%0], [%1], 16;" :: "r"(dst), "l"(src));
}
__device__ __forceinline__ void cp_commit() {
    asm volatile("cp.async.commit_group;" ::: "memory");
}
__device__ __forceinline__ void cp_wait0() {
    asm volatile("cp.async.wait_group 0;" ::: "memory");
}
__device__ __forceinline__ void ldsm4(uint32_t* r, uint32_t a) {
    asm volatile("ldmatrix.sync.aligned.m8n8.x4.shared.b16 {%0,%1,%2,%3}, [%4];"
                 : "=r"(r[0]), "=r"(r[1]), "=r"(r[2]), "=r"(r[3]) : "r"(a));
}
__device__ __forceinline__ void ldsm2(uint32_t* r, uint32_t a) {
    asm volatile("ldmatrix.sync.aligned.m8n8.x2.shared.b16 {%0,%1}, [%2];"
                 : "=r"(r[0]), "=r"(r[1]) : "r"(a));
}
__device__ __forceinline__ void mma_f16(float* c, const uint32_t* a,
                                        uint32_t b0, uint32_t b1) {
    asm("mma.sync.aligned.m16n8k16.row.col.f32.f16.f16.f32 "
        "{%0,%1,%2,%3},{%4,%5,%6,%7},{%8,%9},{%0,%1,%2,%3};"
        : "+f"(c[0]), "+f"(c[1]), "+f"(c[2]), "+f"(c[3])
        : "r"(a[0]), "r"(a[1]), "r"(a[2]), "r"(a[3]), "r"(b0), "r"(b1));
}
__device__ __forceinline__ uint32_t hfpack(float x, float y) {
    __half2 h = __floats2half2_rn(x, y);
    return *reinterpret_cast<uint32_t*>(&h);
}

__global__ void __launch_bounds__(NT, 1)
sigma_mma_kernel(const float* __restrict__ s,
                 const float* __restrict__ a,
                 const float* __restrict__ W1,
                 const float* __restrict__ b1,
                 const float* __restrict__ W2,
                 const float* __restrict__ b2,
                 float* __restrict__ out) {
    extern __shared__ char smem[];
    uint32_t* W2H32 = (uint32_t*)(smem + OFF_W2H);
    uint32_t* HH32  = (uint32_t*)(smem + OFF_HH);
    float*    sTri  = (float*)(smem + OFF_TRI);
    float*    sX    = (float*)(smem + OFF_X);
    float*    sW1   = (float*)(smem + OFF_W1);
    float*    sB1   = (float*)(smem + OFF_B1);
    float*    sB2   = (float*)(smem + OFF_B2);
    int*      sTbl  = (int*)(smem + OFF_TBL);

    const int tid = threadIdx.x;
    const uint32_t sXaddr = smem_u32p(sX);

    // ================= one-time staging =================
    // W2 [528][64] fp32 -> fp16, row stride 72 halves
    for (int idx = tid; idx < TRI * 32; idx += NT) {
        int t = idx >> 5, kw = idx & 31;
        float2 w = *reinterpret_cast<const float2*>(&W2[t * HID + kw * 2]);
        W2H32[t * WS32 + kw] = hfpack(w.x, w.y);
    }
    for (int idx = tid; idx < (NCOLS - TRI) * WS32; idx += NT) {
        int t = TRI + idx / WS32, kw = idx % WS32;
        W2H32[t * WS32 + kw] = 0u;
    }
    // W1 [64][40] copied as-is (k-major), row pad 44
    for (int idx = tid; idx < HID * 10; idx += NT) {
        int hh = idx / 10, k4 = idx - hh * 10;
        float4 w = *reinterpret_cast<const float4*>(&W1[hh * INDIM + k4 * 4]);
        *reinterpret_cast<float4*>(&sW1[hh * XPAD + k4 * 4]) = w;
    }
    if (tid < HID) sB1[tid] = b1[tid];
    for (int idx = tid; idx < NCOLS; idx += NT)
        sB2[idx] = (idx < TRI) ? b2[idx] : 0.0f;
    for (int o = tid; o < 1024; o += NT) {
        int i = o >> 5, j = o & 31;
        int ii = (i < j) ? i : j;
        int jj = (i < j) ? j : i;
        int t = ii * 32 - ((ii * (ii + 1)) >> 1) + jj;
        sTbl[o] = t | ((i == j) ? (1 << 16) : 0);
    }

    // prefetch X for first tile
    const int tile0 = blockIdx.x;
    {
        int row0 = tile0 * ROWS;
        if (tid < 512) {
            int r = tid >> 3, c4 = tid & 7;
            cp16(sXaddr + (r * XPAD + c4 * 4) * 4, &s[(size_t)(row0 + r) * SDIM + c4 * 4]);
        } else if (tid < 640) {
            int t2 = tid - 512, r2 = t2 >> 1, d4 = t2 & 1;
            cp16(sXaddr + (r2 * XPAD + SDIM + d4 * 4) * 4,
                 &a[(size_t)(row0 + r2) * ADIM + d4 * 4]);
        }
        cp_commit();
    }
    cp_wait0();
    __syncthreads();

    // MMA mapping: 32 warps = 4 M-blocks(16r) x 8 N-blocks(72c = 9 n8-tiles).
    const int wi   = tid >> 5, lane = tid & 31;
    const int rb   = wi >> 3,  cb   = wi & 7;
    const int l4   = lane >> 2, lm  = lane & 3;
    const int wcol = cb * 72;

    const uint32_t hhBase = smem_u32p(HH32);
    const uint32_t w2Base = smem_u32p(W2H32);
    const uint32_t aAddr = hhBase +
        (((rb * 16 + (lane & 15)) * WS32 + ((lane >> 4) << 2)) << 2);
    const uint32_t bAddr = w2Base +
        (((wcol + (lane & 7) + ((lane & 16) >> 1)) * WS32 + (((lane >> 3) & 1) << 2)) << 2);
    const uint32_t b8Addr = w2Base +
        (((wcol + 64 + (lane & 7)) * WS32 + (((lane >> 3) & 1) << 2)) << 2);

    // P1 mapping: 32 warps = 8 row-blocks(8r) x 4 col-blocks(16c);
    // thread: rows r0,r0+1; cols c0,c0+1.
    const int p1r0 = (wi & 7) * 8 + 2 * (lane >> 3);
    const int p1c0 = (wi >> 3) * 16 + 2 * (lane & 7);

    // hoisted scatter constants (tile-invariant)
    const int4 tt = ((const int4*)sTbl)[tid & 255];
    const int to0 = tt.x & 0xffff, to1 = tt.y & 0xffff;
    const int to2 = tt.z & 0xffff, to3 = tt.w & 0xffff;
    const int fl0 = tt.x >> 16, fl1 = tt.y >> 16, fl2 = tt.z >> 16, fl3 = tt.w >> 16;
    const float* const trBase = &sTri[(tid >> 8) * TPAD];
    // writer: stage (rb>>1); chunk rows (rb&1)*16 + l4 and +8
    float* const trW0 = &sTri[((rb & 1) * 16 + l4) * TPAD + wcol + 2 * lm];
    float* const trW1 = trW0 + 8 * TPAD;

    // ================= persistent tile loop =================
#pragma unroll 1
    for (int tile = tile0; tile < NTILES; tile += GRID) {
        const int row0 = tile * ROWS;

        // ---- Phase 1: H = relu(X @ W1^T + b1) -> fp16 (broadcast-tiled) ----
        {
            u64 a00 = pack2(sB1[p1c0], 0.f);
            u64 a01 = pack2(sB1[p1c0 + 1], 0.f);
            u64 a10 = a00, a11 = a01;
            const ulonglong2* xr0 = reinterpret_cast<const ulonglong2*>(&sX[p1r0 * XPAD]);
            const ulonglong2* xr1 = reinterpret_cast<const ulonglong2*>(&sX[(p1r0 + 1) * XPAD]);
            const ulonglong2* wc0 = reinterpret_cast<const ulonglong2*>(&sW1[p1c0 * XPAD]);
            const ulonglong2* wc1 = reinterpret_cast<const ulonglong2*>(&sW1[(p1c0 + 1) * XPAD]);
#pragma unroll
            for (int k4 = 0; k4 < 10; ++k4) {
                const ulonglong2 xa = xr0[k4];
                const ulonglong2 xb = xr1[k4];
                const ulonglong2 wa = wc0[k4];
                const ulonglong2 wb = wc1[k4];
                fma2(a00, xa.x, wa.x); fma2(a00, xa.y, wa.y);
                fma2(a01, xa.x, wb.x); fma2(a01, xa.y, wb.y);
                fma2(a10, xb.x, wa.x); fma2(a10, xb.y, wa.y);
                fma2(a11, xb.x, wb.x); fma2(a11, xb.y, wb.y);
            }
            float e, o;
            unpack2(a00, e, o); const float h00 = fmaxf(e + o, 0.f);
            unpack2(a01, e, o); const float h01 = fmaxf(e + o, 0.f);
            unpack2(a10, e, o); const float h10 = fmaxf(e + o, 0.f);
            unpack2(a11, e, o); const float h11 = fmaxf(e + o, 0.f);
            const int wword = (p1c0 >> 1);
            HH32[p1r0 * WS32 + wword]       = hfpack(h00, h01);
            HH32[(p1r0 + 1) * WS32 + wword] = hfpack(h10, h11);
        }
        __syncthreads();   // H visible; sX free for prefetch

        // ---- prefetch X of next tile ----
        if (tile + GRID < NTILES) {
            int nrow0 = (tile + GRID) * ROWS;
            if (tid < 512) {
                int r = tid >> 3, c4 = tid & 7;
                cp16(sXaddr + (r * XPAD + c4 * 4) * 4,
                     &s[(size_t)(nrow0 + r) * SDIM + c4 * 4]);
            } else if (tid < 640) {
                int t2 = tid - 512, r2 = t2 >> 1, d4 = t2 & 1;
                cp16(sXaddr + (r2 * XPAD + SDIM + d4 * 4) * 4,
                     &a[(size_t)(nrow0 + r2) * ADIM + d4 * 4]);
            }
            cp_commit();
        }

        // ---- Phase 2: tri = H @ W2^T + b2 (HMMA fp16) ----
        float c[9][4];
#pragma unroll
        for (int j = 0; j < 9; ++j) {
            float2 bb = *reinterpret_cast<const float2*>(&sB2[wcol + j * 8 + 2 * lm]);
            c[j][0] = bb.x; c[j][1] = bb.y;
            c[j][2] = bb.x; c[j][3] = bb.y;
        }
#pragma unroll
        for (int kk = 0; kk < 4; ++kk) {
            const uint32_t kb = kk * 32;
            uint32_t ah[4];
            ldsm4(ah, aAddr + kb);
#pragma unroll
            for (int p = 0; p < 4; ++p) {
                uint32_t bh[4];
                ldsm4(bh, bAddr + p * 2304 + kb);
                mma_f16(c[2 * p],     ah, bh[0], bh[1]);
                mma_f16(c[2 * p + 1], ah, bh[2], bh[3]);
            }
            {
                uint32_t bh[2];
                ldsm2(bh, b8Addr + kb);
                mma_f16(c[8], ah, bh[0], bh[1]);
            }
        }

        // ---- Phase 3: 2 stages of 32 rows via smem chunk + table scatter ----
        // Stage st covers rows [32st, 32st+32): writers rb>>1 == st.
#pragma unroll
        for (int st = 0; st < 2; ++st) {
            if ((rb >> 1) == st) {
#pragma unroll
                for (int j = 0; j < 9; ++j) {
                    *reinterpret_cast<float2*>(trW0 + j * 8) = make_float2(c[j][0], c[j][1]);
                    *reinterpret_cast<float2*>(trW1 + j * 8) = make_float2(c[j][2], c[j][3]);
                }
            }
            __syncthreads();

            float4* out4 = reinterpret_cast<float4*>(out + (size_t)(row0 + st * 32) * 1024);
#pragma unroll
            for (int it = 0; it < 8; ++it) {
                const float* tr = trBase + it * 4 * TPAD;
                float v0 = tr[to0], v1 = tr[to1], v2 = tr[to2], v3 = tr[to3];
                if (fl0) v0 = __expf(v0);
                if (fl1) v1 = __expf(v1);
                if (fl2) v2 = __expf(v2);
                if (fl3) v3 = __expf(v3);
                out4[tid + it * NT] = make_float4(v0, v1, v2, v3);
            }
            if (st == 1) cp_wait0();
            __syncthreads();
        }
    }
}

extern "C" void kernel_launch(void* const* d_in, const int* in_sizes, int n_in,
                              void* d_out, int out_size) {
    (void)in_sizes; (void)n_in; (void)out_size;
    const float* s  = (const float*)d_in[0];
    const float* a  = (const float*)d_in[1];
    const float* W1 = (const float*)d_in[2];
    const float* b1 = (const float*)d_in[3];
    const float* W2 = (const float*)d_in[4];
    const float* b2 = (const float*)d_in[5];
    float* out = (float*)d_out;

    cudaFuncSetAttribute(sigma_mma_kernel,
                         cudaFuncAttributeMaxDynamicSharedMemorySize, SMEM_BYTES);
    sigma_mma_kernel<<<GRID, NT, SMEM_BYTES>>>(s, a, W1, b1, W2, b2, out);
}